// round 10
// baseline (speedup 1.0000x reference)
#include <cuda_runtime.h>
#include <cuda_fp16.h>
#include <cstdint>

// ---------------- scratch (static, no allocations) ----------------
#define MAXN 1000000
#define MAXG 1000
#define HS 8    // halves per row (16B) for h and agg
#define EPB 512 // edges per block (bulk-copy chunk)
#define TPB 256

__device__ __half g_h[MAXN * HS];    // hidden state, fp16 padded rows (16B)
__device__ __half g_agg[MAXN * HS];  // aggregation buffer, fp16 (16B rows)
__device__ float  g_pool[MAXG * 6];
__device__ float  g_cnt[MAXG];

// one 16B fp16 vector reduction: 8 halves (sm_90+)
__device__ __forceinline__ void red8h(__half* p, unsigned r0, unsigned r1,
                                      unsigned r2, unsigned r3) {
    asm volatile("red.global.add.noftz.v4.f16x2 [%0], {%1, %2, %3, %4};"
                 :: "l"(p), "r"(r0), "r"(r1), "r"(r2), "r"(r3) : "memory");
}

__device__ __forceinline__ unsigned pack2(float a, float b) {
    __half2 h = __floats2half2_rn(a, b);
    return *reinterpret_cast<unsigned*>(&h);
}
__device__ __forceinline__ float2 unpack2(unsigned u) {
    return __half22float2(*reinterpret_cast<__half2*>(&u));
}

__device__ __forceinline__ unsigned smem_u32(const void* p) {
    unsigned a;
    asm("{ .reg .u64 t; cvta.to.shared.u64 t, %1; cvt.u32.u64 %0, t; }"
        : "=r"(a) : "l"(p));
    return a;
}

// plain bulk async copy gmem -> smem (bypasses L1), completion via mbarrier tx
__device__ __forceinline__ void bulk_g2s(unsigned smem_dst, const void* gsrc,
                                         unsigned bytes, unsigned mbar) {
    asm volatile(
        "cp.async.bulk.shared::cluster.global.mbarrier::complete_tx::bytes "
        "[%0], [%1], %2, [%3];"
        :: "r"(smem_dst), "l"(gsrc), "r"(bytes), "r"(mbar) : "memory");
}

// half2 message path: m = hmax2(hadd2(h2, cvt(e2)), 0)
__device__ __forceinline__ void emit_msg_h2(__half* o, uint4 hv,
                                            float e0, float e1, float e2,
                                            float e3, float e4, float e5) {
    __half2 z = __floats2half2_rn(0.f, 0.f);
    __half2 h0 = *reinterpret_cast<__half2*>(&hv.x);
    __half2 h1 = *reinterpret_cast<__half2*>(&hv.y);
    __half2 h2 = *reinterpret_cast<__half2*>(&hv.z);
    __half2 m0 = __hmax2(__hadd2(h0, __floats2half2_rn(e0, e1)), z);
    __half2 m1 = __hmax2(__hadd2(h1, __floats2half2_rn(e2, e3)), z);
    __half2 m2 = __hmax2(__hadd2(h2, __floats2half2_rn(e4, e5)), z);
    red8h(o, *reinterpret_cast<unsigned*>(&m0),
             *reinterpret_cast<unsigned*>(&m1),
             *reinterpret_cast<unsigned*>(&m2), 0u);
}

// ---------------- kernels ----------------

// copy x -> fp16 g_h, zero g_agg / g_pool / g_cnt
__global__ __launch_bounds__(256)
void prep_kernel(const float* __restrict__ x, int N) {
    int n = blockIdx.x * blockDim.x + threadIdx.x;
    if (n < MAXG * 6) g_pool[n] = 0.f;
    if (n < MAXG) g_cnt[n] = 0.f;
    if (n >= N) return;
    const float2* xp = (const float2*)(x + 6ll * n);
    float2 x0 = __ldcs(xp), x1 = __ldcs(xp + 1), x2 = __ldcs(xp + 2);
    uint4 hv;
    hv.x = pack2(x0.x, x0.y);
    hv.y = pack2(x1.x, x1.y);
    hv.z = pack2(x2.x, x2.y);
    hv.w = 0u;
    *(uint4*)(g_h + (long long)HS * n) = hv;
    *(uint4*)(g_agg + (long long)HS * n) = make_uint4(0u, 0u, 0u, 0u);
}

// message + aggregate: agg[dst] += relu(h[src] + edge_attr)
// Streams (idx + ea) arrive via cp.async.bulk into smem (L1 untouched);
// gathers use default LDG (L1-allocating). 2 edges per thread.
__global__ __launch_bounds__(TPB)
void edge_kernel(const __half* __restrict__ h,
                 const int* __restrict__ src,
                 const int* __restrict__ dst,
                 const float* __restrict__ ea,
                 __half* __restrict__ agg, int E)
{
    __shared__ __align__(16) float s_ea[EPB * 6];   // 12288 B
    __shared__ __align__(16) int   s_src[EPB];      //  2048 B
    __shared__ __align__(16) int   s_dst[EPB];      //  2048 B
    __shared__ __align__(8)  unsigned long long s_mbar;

    int base = blockIdx.x * EPB;
    int cnt = E - base; if (cnt > EPB) cnt = EPB;

    if (cnt == EPB) {
        unsigned mbar = smem_u32(&s_mbar);
        if (threadIdx.x == 0) {
            asm volatile("mbarrier.init.shared.b64 [%0], %1;"
                         :: "r"(mbar), "r"(1u) : "memory");
        }
        __syncthreads();
        if (threadIdx.x == 0) {
            unsigned bytes = EPB * 24u + EPB * 4u + EPB * 4u;
            asm volatile("mbarrier.arrive.expect_tx.shared.b64 _, [%0], %1;"
                         :: "r"(mbar), "r"(bytes) : "memory");
            bulk_g2s(smem_u32(s_ea),  ea  + (long long)base * 6, EPB * 24u, mbar);
            bulk_g2s(smem_u32(s_src), src + base, EPB * 4u, mbar);
            bulk_g2s(smem_u32(s_dst), dst + base, EPB * 4u, mbar);
        }
        // wait (acquire) for all tx bytes
        {
            unsigned done;
            asm volatile(
                "{\n\t.reg .pred p;\n\t"
                "mbarrier.try_wait.parity.acquire.cta.shared::cta.b64 p, [%1], 0;\n\t"
                "selp.b32 %0, 1, 0, p;\n\t}"
                : "=r"(done) : "r"(mbar) : "memory");
            if (!done) {
                asm volatile(
                    "{\n\t.reg .pred P1;\n\t"
                    "W_%=:\n\t"
                    "mbarrier.try_wait.parity.acquire.cta.shared::cta.b64 P1, [%0], 0, 0x989680;\n\t"
                    "@P1 bra.uni D_%=;\n\t"
                    "bra.uni W_%=;\n\t"
                    "D_%=:\n\t}"
                    :: "r"(mbar) : "memory");
            }
        }

        int t = threadIdx.x;
        int s0 = s_src[2 * t],     s1 = s_src[2 * t + 1];
        int d0 = s_dst[2 * t],     d1 = s_dst[2 * t + 1];
        float4 a0 = *(const float4*)(s_ea + 12 * t);
        float4 a1 = *(const float4*)(s_ea + 12 * t + 4);
        float4 a2 = *(const float4*)(s_ea + 12 * t + 8);

        uint4 hv0 = __ldg((const uint4*)(h + (long long)HS * s0));
        uint4 hv1 = __ldg((const uint4*)(h + (long long)HS * s1));

        emit_msg_h2(agg + (long long)HS * d0, hv0,
                    a0.x, a0.y, a0.z, a0.w, a1.x, a1.y);
        emit_msg_h2(agg + (long long)HS * d1, hv1,
                    a1.z, a1.w, a2.x, a2.y, a2.z, a2.w);
    } else {
        // tail block: direct global loads, 1 edge per thread, strided
        for (int e = base + threadIdx.x; e < E; e += TPB) {
            int s = __ldcs(src + e), d = __ldcs(dst + e);
            const float2* aep = (const float2*)(ea + 6ll * e);
            float2 b0 = __ldcs(aep), b1 = __ldcs(aep + 1), b2 = __ldcs(aep + 2);
            uint4 hv = __ldg((const uint4*)(h + (long long)HS * s));
            emit_msg_h2(agg + (long long)HS * d, hv,
                        b0.x, b0.y, b1.x, b1.y, b2.x, b2.y);
        }
    }
}

// update: hout = relu((hin + agg) @ W + b); zero agg for next layer
__global__ __launch_bounds__(256)
void node_kernel(const __half* __restrict__ hin,
                 __half* __restrict__ agg,
                 const float* __restrict__ W,
                 const float* __restrict__ b,
                 __half* __restrict__ hout, int N)
{
    int n = blockIdx.x * blockDim.x + threadIdx.x;
    if (n >= N) return;
    uint4 hv = *(const uint4*)(hin + (long long)HS * n);
    uint4* gp = (uint4*)(agg + (long long)HS * n);
    uint4 gv = *gp;
    *gp = make_uint4(0u, 0u, 0u, 0u);

    float2 h0 = unpack2(hv.x), h1 = unpack2(hv.y), h2 = unpack2(hv.z);
    float2 q0 = unpack2(gv.x), q1 = unpack2(gv.y), q2 = unpack2(gv.z);
    float t[6] = { h0.x + q0.x, h0.y + q0.y, h1.x + q1.x,
                   h1.y + q1.y, h2.x + q2.x, h2.y + q2.y };

    float o[6];
    #pragma unroll
    for (int j = 0; j < 6; j++) {
        float acc = __ldg(b + j);
        #pragma unroll
        for (int i = 0; i < 6; i++) acc += t[i] * __ldg(W + i * 6 + j);
        o[j] = fmaxf(acc, 0.f);
    }
    uint4 ov;
    ov.x = pack2(o[0], o[1]);
    ov.y = pack2(o[2], o[3]);
    ov.z = pack2(o[4], o[5]);
    ov.w = 0u;
    *(uint4*)(hout + (long long)HS * n) = ov;
}

// layer-3 update fused with mean-pool accumulation (batch is sorted).
__global__ __launch_bounds__(256)
void node3_pool_kernel(const __half* __restrict__ hin,
                       const __half* __restrict__ agg,
                       const float* __restrict__ W,
                       const float* __restrict__ b,
                       const int* __restrict__ batch, int N)
{
    int n = blockIdx.x * blockDim.x + threadIdx.x;
    bool valid = (n < N);
    int nn = valid ? n : (N - 1);

    uint4 hv = *(const uint4*)(hin + (long long)HS * nn);
    uint4 gv = *(const uint4*)(agg + (long long)HS * nn);

    float2 h0 = unpack2(hv.x), h1 = unpack2(hv.y), h2 = unpack2(hv.z);
    float2 q0 = unpack2(gv.x), q1 = unpack2(gv.y), q2 = unpack2(gv.z);
    float t[6] = { h0.x + q0.x, h0.y + q0.y, h1.x + q1.x,
                   h1.y + q1.y, h2.x + q2.x, h2.y + q2.y };

    float o[6];
    #pragma unroll
    for (int j = 0; j < 6; j++) {
        float acc = __ldg(b + j);
        #pragma unroll
        for (int i = 0; i < 6; i++) acc += t[i] * __ldg(W + i * 6 + j);
        o[j] = valid ? acc : 0.f;
    }
    float c = valid ? 1.f : 0.f;
    int g = __ldg(batch + nn);

    unsigned lane = threadIdx.x & 31u;
    unsigned peers = __match_any_sync(0xffffffffu, g);  // contiguous (sorted)
    int leader = __ffs(peers) - 1;

    #pragma unroll
    for (int j = 0; j < 6; j++) {
        float v = o[j];
        #pragma unroll
        for (int off = 1; off < 32; off <<= 1) {
            float tv = __shfl_down_sync(0xffffffffu, v, off);
            if (lane + off < 32 && ((peers >> (lane + off)) & 1u)) v += tv;
        }
        if ((int)lane == leader) atomicAdd(&g_pool[g * 6 + j], v);
    }
    {
        float v = c;
        #pragma unroll
        for (int off = 1; off < 32; off <<= 1) {
            float tv = __shfl_down_sync(0xffffffffu, v, off);
            if (lane + off < 32 && ((peers >> (lane + off)) & 1u)) v += tv;
        }
        if ((int)lane == leader) atomicAdd(&g_cnt[g], v);
    }
}

__global__ void final_kernel(const float* __restrict__ Wl,
                             const float* __restrict__ bl,
                             float* __restrict__ out, int G)
{
    int g = blockIdx.x * blockDim.x + threadIdx.x;
    if (g >= G) return;
    float c = fmaxf(g_cnt[g], 1.f);
    float s = 0.f;
    #pragma unroll
    for (int i = 0; i < 6; i++) s += (g_pool[g * 6 + i] / c) * __ldg(Wl + i);
    out[g] = s + __ldg(bl);
}

// ---------------- launch ----------------

extern "C" void kernel_launch(void* const* d_in, const int* in_sizes, int n_in,
                              void* d_out, int out_size)
{
    const float* x     = (const float*)d_in[0];
    const int*   ei    = (const int*)d_in[1];     // int32 (JAX demotes int64)
    const float* ea    = (const float*)d_in[2];
    const int*   batch = (const int*)d_in[3];
    const float* W1 = (const float*)d_in[4];
    const float* b1 = (const float*)d_in[5];
    const float* W2 = (const float*)d_in[6];
    const float* b2 = (const float*)d_in[7];
    const float* W3 = (const float*)d_in[8];
    const float* b3 = (const float*)d_in[9];
    const float* Wl = (const float*)d_in[10];
    const float* bl = (const float*)d_in[11];
    float* out = (float*)d_out;

    int N = in_sizes[0] / 6;
    int E = in_sizes[1] / 2;
    int G = out_size;

    const int* src = ei;
    const int* dst = ei + E;

    __half* h;   cudaGetSymbolAddress((void**)&h,   g_h);
    __half* agg; cudaGetSymbolAddress((void**)&agg, g_agg);

    int nb_node = (N + 255) / 256;
    int nb_edge = (E + EPB - 1) / EPB;

    prep_kernel<<<nb_node, 256>>>(x, N);

    // layer 1 (h_in = fp16 x, already in g_h)
    edge_kernel<<<nb_edge, TPB>>>(h, src, dst, ea, agg, E);
    node_kernel<<<nb_node, 256>>>(h, agg, W1, b1, h, N);

    // layer 2
    edge_kernel<<<nb_edge, TPB>>>(h, src, dst, ea, agg, E);
    node_kernel<<<nb_node, 256>>>(h, agg, W2, b2, h, N);

    // layer 3 + pooling (fused)
    edge_kernel<<<nb_edge, TPB>>>(h, src, dst, ea, agg, E);
    node3_pool_kernel<<<nb_node, 256>>>(h, agg, W3, b3, batch, N);

    final_kernel<<<(G + 127) / 128, 128>>>(Wl, bl, out, G);
}

// round 11
// speedup vs baseline: 1.1626x; 1.1626x over previous
#include <cuda_runtime.h>
#include <cuda_fp16.h>

// ---------------- scratch (static, no allocations) ----------------
#define MAXN 1000000
#define MAXG 1000
#define HS 8   // halves per row (16B) for h and agg

__device__ __half g_h[MAXN * HS];    // hidden state, fp16 padded rows (16B)
__device__ __half g_agg[MAXN * HS];  // aggregation buffer, fp16 (16B rows)
__device__ float  g_pool[MAXG * 6];
__device__ float  g_cnt[MAXG];

// one 16B fp16 vector reduction: 8 halves (sm_90+)
__device__ __forceinline__ void red8h(__half* p, unsigned r0, unsigned r1,
                                      unsigned r2, unsigned r3) {
    asm volatile("red.global.add.noftz.v4.f16x2 [%0], {%1, %2, %3, %4};"
                 :: "l"(p), "r"(r0), "r"(r1), "r"(r2), "r"(r3) : "memory");
}

__device__ __forceinline__ unsigned pack2(float a, float b) {
    __half2 h = __floats2half2_rn(a, b);
    return *reinterpret_cast<unsigned*>(&h);
}
__device__ __forceinline__ float2 unpack2(unsigned u) {
    return __half22float2(*reinterpret_cast<__half2*>(&u));
}

// half2 message path: m = hmax2(hadd2(h2, cvt(e2)), 0)
__device__ __forceinline__ void emit_msg_h2(__half* o, uint4 hv,
                                            float e0, float e1, float e2,
                                            float e3, float e4, float e5) {
    __half2 z = __floats2half2_rn(0.f, 0.f);
    __half2 h0 = *reinterpret_cast<__half2*>(&hv.x);
    __half2 h1 = *reinterpret_cast<__half2*>(&hv.y);
    __half2 h2 = *reinterpret_cast<__half2*>(&hv.z);
    __half2 m0 = __hmax2(__hadd2(h0, __floats2half2_rn(e0, e1)), z);
    __half2 m1 = __hmax2(__hadd2(h1, __floats2half2_rn(e2, e3)), z);
    __half2 m2 = __hmax2(__hadd2(h2, __floats2half2_rn(e4, e5)), z);
    red8h(o, *reinterpret_cast<unsigned*>(&m0),
             *reinterpret_cast<unsigned*>(&m1),
             *reinterpret_cast<unsigned*>(&m2), 0u);
}

// ---------------- kernels ----------------

// copy x -> fp16 g_h, zero g_agg / g_pool / g_cnt
__global__ __launch_bounds__(256)
void prep_kernel(const float* __restrict__ x, int N) {
    int n = blockIdx.x * blockDim.x + threadIdx.x;
    if (n < MAXG * 6) g_pool[n] = 0.f;
    if (n < MAXG) g_cnt[n] = 0.f;
    if (n >= N) return;
    const float2* xp = (const float2*)(x + 6ll * n);
    float2 x0 = __ldcs(xp), x1 = __ldcs(xp + 1), x2 = __ldcs(xp + 2);
    uint4 hv;
    hv.x = pack2(x0.x, x0.y);
    hv.y = pack2(x1.x, x1.y);
    hv.z = pack2(x2.x, x2.y);
    hv.w = 0u;
    *(uint4*)(g_h + (long long)HS * n) = hv;
    *(uint4*)(g_agg + (long long)HS * n) = make_uint4(0u, 0u, 0u, 0u);
}

// message + aggregate, 2 edges per thread:
// agg[dst] += relu(h[src] + edge_attr)   (single v4.f16x2 red per edge)
__global__ __launch_bounds__(256)
void edge_kernel(const __half* __restrict__ h,
                 const int* __restrict__ src,
                 const int* __restrict__ dst,
                 const float* __restrict__ ea,
                 __half* __restrict__ agg, int E)
{
    int t = blockIdx.x * blockDim.x + threadIdx.x;
    int e0 = 2 * t;
    if (e0 >= E) return;
    bool has2 = (e0 + 1 < E);

    int2 s2 = __ldcs((const int2*)(src + e0));
    int2 d2 = __ldcs((const int2*)(dst + e0));

    const float4* ap = (const float4*)(ea + 12ll * t);  // 48B for 2 edges
    float4 a0 = __ldcs(ap + 0);
    float4 a1 = __ldcs(ap + 1);
    float4 a2 = has2 ? __ldcs(ap + 2) : make_float4(0.f, 0.f, 0.f, 0.f);

    // gathers: default caching (L1 allocate) — aggregate L1 holds h
    uint4 hv0 = __ldg((const uint4*)(h + (long long)HS * s2.x));
    uint4 hv1 = has2 ? __ldg((const uint4*)(h + (long long)HS * s2.y))
                     : make_uint4(0u, 0u, 0u, 0u);

    emit_msg_h2(agg + (long long)HS * d2.x, hv0,
                a0.x, a0.y, a0.z, a0.w, a1.x, a1.y);
    if (has2)
        emit_msg_h2(agg + (long long)HS * d2.y, hv1,
                    a1.z, a1.w, a2.x, a2.y, a2.z, a2.w);
}

// update: hout = relu((hin + agg) @ W + b); zero agg for next layer
__global__ __launch_bounds__(256)
void node_kernel(const __half* __restrict__ hin,
                 __half* __restrict__ agg,
                 const float* __restrict__ W,
                 const float* __restrict__ b,
                 __half* __restrict__ hout, int N)
{
    int n = blockIdx.x * blockDim.x + threadIdx.x;
    if (n >= N) return;
    uint4 hv = *(const uint4*)(hin + (long long)HS * n);
    uint4* gp = (uint4*)(agg + (long long)HS * n);
    uint4 gv = *gp;
    *gp = make_uint4(0u, 0u, 0u, 0u);

    float2 h0 = unpack2(hv.x), h1 = unpack2(hv.y), h2 = unpack2(hv.z);
    float2 q0 = unpack2(gv.x), q1 = unpack2(gv.y), q2 = unpack2(gv.z);
    float t[6] = { h0.x + q0.x, h0.y + q0.y, h1.x + q1.x,
                   h1.y + q1.y, h2.x + q2.x, h2.y + q2.y };

    float o[6];
    #pragma unroll
    for (int j = 0; j < 6; j++) {
        float acc = __ldg(b + j);
        #pragma unroll
        for (int i = 0; i < 6; i++) acc += t[i] * __ldg(W + i * 6 + j);
        o[j] = fmaxf(acc, 0.f);
    }
    uint4 ov;
    ov.x = pack2(o[0], o[1]);
    ov.y = pack2(o[2], o[3]);
    ov.z = pack2(o[4], o[5]);
    ov.w = 0u;
    *(uint4*)(hout + (long long)HS * n) = ov;
}

// layer-3 update fused with mean-pool accumulation (batch is sorted).
__global__ __launch_bounds__(256)
void node3_pool_kernel(const __half* __restrict__ hin,
                       const __half* __restrict__ agg,
                       const float* __restrict__ W,
                       const float* __restrict__ b,
                       const int* __restrict__ batch, int N)
{
    int n = blockIdx.x * blockDim.x + threadIdx.x;
    bool valid = (n < N);
    int nn = valid ? n : (N - 1);

    uint4 hv = *(const uint4*)(hin + (long long)HS * nn);
    uint4 gv = *(const uint4*)(agg + (long long)HS * nn);

    float2 h0 = unpack2(hv.x), h1 = unpack2(hv.y), h2 = unpack2(hv.z);
    float2 q0 = unpack2(gv.x), q1 = unpack2(gv.y), q2 = unpack2(gv.z);
    float t[6] = { h0.x + q0.x, h0.y + q0.y, h1.x + q1.x,
                   h1.y + q1.y, h2.x + q2.x, h2.y + q2.y };

    float o[6];
    #pragma unroll
    for (int j = 0; j < 6; j++) {
        float acc = __ldg(b + j);
        #pragma unroll
        for (int i = 0; i < 6; i++) acc += t[i] * __ldg(W + i * 6 + j);
        o[j] = valid ? acc : 0.f;
    }
    float c = valid ? 1.f : 0.f;
    int g = __ldg(batch + nn);

    unsigned lane = threadIdx.x & 31u;
    unsigned peers = __match_any_sync(0xffffffffu, g);  // contiguous (sorted)
    int leader = __ffs(peers) - 1;

    #pragma unroll
    for (int j = 0; j < 6; j++) {
        float v = o[j];
        #pragma unroll
        for (int off = 1; off < 32; off <<= 1) {
            float tv = __shfl_down_sync(0xffffffffu, v, off);
            if (lane + off < 32 && ((peers >> (lane + off)) & 1u)) v += tv;
        }
        if ((int)lane == leader) atomicAdd(&g_pool[g * 6 + j], v);
    }
    {
        float v = c;
        #pragma unroll
        for (int off = 1; off < 32; off <<= 1) {
            float tv = __shfl_down_sync(0xffffffffu, v, off);
            if (lane + off < 32 && ((peers >> (lane + off)) & 1u)) v += tv;
        }
        if ((int)lane == leader) atomicAdd(&g_cnt[g], v);
    }
}

__global__ void final_kernel(const float* __restrict__ Wl,
                             const float* __restrict__ bl,
                             float* __restrict__ out, int G)
{
    int g = blockIdx.x * blockDim.x + threadIdx.x;
    if (g >= G) return;
    float c = fmaxf(g_cnt[g], 1.f);
    float s = 0.f;
    #pragma unroll
    for (int i = 0; i < 6; i++) s += (g_pool[g * 6 + i] / c) * __ldg(Wl + i);
    out[g] = s + __ldg(bl);
}

// ---------------- launch ----------------

extern "C" void kernel_launch(void* const* d_in, const int* in_sizes, int n_in,
                              void* d_out, int out_size)
{
    const float* x     = (const float*)d_in[0];
    const int*   ei    = (const int*)d_in[1];     // int32 (JAX demotes int64)
    const float* ea    = (const float*)d_in[2];
    const int*   batch = (const int*)d_in[3];
    const float* W1 = (const float*)d_in[4];
    const float* b1 = (const float*)d_in[5];
    const float* W2 = (const float*)d_in[6];
    const float* b2 = (const float*)d_in[7];
    const float* W3 = (const float*)d_in[8];
    const float* b3 = (const float*)d_in[9];
    const float* Wl = (const float*)d_in[10];
    const float* bl = (const float*)d_in[11];
    float* out = (float*)d_out;

    int N = in_sizes[0] / 6;
    int E = in_sizes[1] / 2;
    int G = out_size;

    const int* src = ei;
    const int* dst = ei + E;

    __half* h;   cudaGetSymbolAddress((void**)&h,   g_h);
    __half* agg; cudaGetSymbolAddress((void**)&agg, g_agg);

    // maximize L1 carveout for the gather-heavy edge kernel (no smem used)
    static bool carveout_set = false;
    if (!carveout_set) {
        cudaFuncSetAttribute(edge_kernel,
                             cudaFuncAttributePreferredSharedMemoryCarveout, 0);
        carveout_set = true;
    }

    int nb_node = (N + 255) / 256;
    int nb_edge2 = ((E + 1) / 2 + 255) / 256;

    prep_kernel<<<nb_node, 256>>>(x, N);

    // layer 1 (h_in = fp16 x, already in g_h)
    edge_kernel<<<nb_edge2, 256>>>(h, src, dst, ea, agg, E);
    node_kernel<<<nb_node, 256>>>(h, agg, W1, b1, h, N);

    // layer 2
    edge_kernel<<<nb_edge2, 256>>>(h, src, dst, ea, agg, E);
    node_kernel<<<nb_node, 256>>>(h, agg, W2, b2, h, N);

    // layer 3 + pooling (fused)
    edge_kernel<<<nb_edge2, 256>>>(h, src, dst, ea, agg, E);
    node3_pool_kernel<<<nb_node, 256>>>(h, agg, W3, b3, batch, N);

    final_kernel<<<(G + 127) / 128, 128>>>(Wl, bl, out, G);
}